// round 4
// baseline (speedup 1.0000x reference)
#include <cuda_runtime.h>
#include <cstdint>

#define TT 1000
#define BB 512
#define IDM 32
#define HH 64
#define NHIST 5

// Kalman gains per step: layout [t][o*64 + i]  (K[i][o] = g_U[t*192 + o*64 + i])
__device__ __align__(16) float g_U[TT * 192];

// ======================================================================
// Producer: Riccati chain -> K_t. Single block. Early-out on convergence.
// ======================================================================
#define PD 65  // padded stride kills bank conflicts on column reads

struct PSmem {
    float A[64 * PD];
    float cov[64 * PD];
    float E[64 * PD];
    float P[64 * PD];
    float Cs[192];
    float Y[64 * 3];
    float S[9];
    float Si[9];
    float U[192];
    float Up[192];
    float CP[192];
    int ctl[2];   // max|dK| bits, max|K| bits
    int done;
};

__global__ void __launch_bounds__(256, 1)
cov_kernel(const float* __restrict__ W_hh, const float* __restrict__ Cmat) {
    extern __shared__ char praw[];
    PSmem& s = *reinterpret_cast<PSmem*>(praw);
    const int tid = threadIdx.x;

    for (int idx = tid; idx < 4096; idx += 256) {
        int i = idx >> 6, k = idx & 63;
        s.A[i * PD + k]   = W_hh[idx];
        s.cov[i * PD + k] = (i == k) ? 1.f : 0.f;
    }
    for (int idx = tid; idx < 192; idx += 256) { s.Cs[idx] = Cmat[idx]; s.Up[idx] = 0.f; }
    if (tid < 2) s.ctl[tid] = 0;
    if (tid == 0) s.done = 0;
    __syncthreads();

    const int ty = tid >> 4;   // 0..15
    const int tx = tid & 15;   // 0..15

    for (int t = NHIST; t < TT; t++) {
        // ---- E = A @ cov ----
        {
            float acc[4][4] = {};
            for (int k = 0; k < 64; k++) {
                float a0 = s.A[(ty * 4 + 0) * PD + k];
                float a1 = s.A[(ty * 4 + 1) * PD + k];
                float a2 = s.A[(ty * 4 + 2) * PD + k];
                float a3 = s.A[(ty * 4 + 3) * PD + k];
                float b0 = s.cov[k * PD + tx * 4 + 0];
                float b1 = s.cov[k * PD + tx * 4 + 1];
                float b2 = s.cov[k * PD + tx * 4 + 2];
                float b3 = s.cov[k * PD + tx * 4 + 3];
                acc[0][0] += a0 * b0; acc[0][1] += a0 * b1; acc[0][2] += a0 * b2; acc[0][3] += a0 * b3;
                acc[1][0] += a1 * b0; acc[1][1] += a1 * b1; acc[1][2] += a1 * b2; acc[1][3] += a1 * b3;
                acc[2][0] += a2 * b0; acc[2][1] += a2 * b1; acc[2][2] += a2 * b2; acc[2][3] += a2 * b3;
                acc[3][0] += a3 * b0; acc[3][1] += a3 * b1; acc[3][2] += a3 * b2; acc[3][3] += a3 * b3;
            }
            for (int rr = 0; rr < 4; rr++)
                for (int cc = 0; cc < 4; cc++)
                    s.E[(ty * 4 + rr) * PD + tx * 4 + cc] = acc[rr][cc];
        }
        __syncthreads();

        // ---- P = E @ A^T ----
        {
            float acc[4][4] = {};
            for (int k = 0; k < 64; k++) {
                float a0 = s.E[(ty * 4 + 0) * PD + k];
                float a1 = s.E[(ty * 4 + 1) * PD + k];
                float a2 = s.E[(ty * 4 + 2) * PD + k];
                float a3 = s.E[(ty * 4 + 3) * PD + k];
                float b0 = s.A[(tx * 4 + 0) * PD + k];
                float b1 = s.A[(tx * 4 + 1) * PD + k];
                float b2 = s.A[(tx * 4 + 2) * PD + k];
                float b3 = s.A[(tx * 4 + 3) * PD + k];
                acc[0][0] += a0 * b0; acc[0][1] += a0 * b1; acc[0][2] += a0 * b2; acc[0][3] += a0 * b3;
                acc[1][0] += a1 * b0; acc[1][1] += a1 * b1; acc[1][2] += a1 * b2; acc[1][3] += a1 * b3;
                acc[2][0] += a2 * b0; acc[2][1] += a2 * b1; acc[2][2] += a2 * b2; acc[2][3] += a2 * b3;
                acc[3][0] += a3 * b0; acc[3][1] += a3 * b1; acc[3][2] += a3 * b2; acc[3][3] += a3 * b3;
            }
            for (int rr = 0; rr < 4; rr++)
                for (int cc = 0; cc < 4; cc++)
                    s.P[(ty * 4 + rr) * PD + tx * 4 + cc] = acc[rr][cc];
        }
        __syncthreads();

        // ---- Y = P @ C^T (64x3) ----
        if (tid < 192) {
            int o = tid >> 6, i = tid & 63;
            float acc = 0.f;
            for (int k = 0; k < 64; k++) acc += s.P[i * PD + k] * s.Cs[o * 64 + k];
            s.Y[i * 3 + o] = acc;
        }
        __syncthreads();

        // ---- S = C @ Y + I (3x3) ----
        if (tid < 9) {
            int o1 = tid / 3, o2 = tid - o1 * 3;
            float acc = (o1 == o2) ? 1.f : 0.f;
            for (int k = 0; k < 64; k++) acc += s.Cs[o1 * 64 + k] * s.Y[k * 3 + o2];
            s.S[tid] = acc;
        }
        __syncthreads();

        // ---- Si = inv(S) (adjugate) ----
        if (tid == 0) {
            float a = s.S[0], b = s.S[1], c = s.S[2];
            float d = s.S[3], e = s.S[4], f = s.S[5];
            float g = s.S[6], h = s.S[7], i2 = s.S[8];
            float A0 =  (e * i2 - f * h);
            float A1 = -(d * i2 - f * g);
            float A2 =  (d * h  - e * g);
            float B0 = -(b * i2 - c * h);
            float B1 =  (a * i2 - c * g);
            float B2 = -(a * h  - b * g);
            float C0 =  (b * f - c * e);
            float C1 = -(a * f - c * d);
            float C2 =  (a * e - b * d);
            float det = a * A0 + b * A1 + c * A2;
            float id = 1.f / det;
            s.Si[0] = A0 * id; s.Si[1] = B0 * id; s.Si[2] = C0 * id;
            s.Si[3] = A1 * id; s.Si[4] = B1 * id; s.Si[5] = C1 * id;
            s.Si[6] = A2 * id; s.Si[7] = B2 * id; s.Si[8] = C2 * id;
        }
        __syncthreads();

        // ---- U = Y @ Si  (= K^T), store, track convergence ----
        if (tid < 192) {
            int o = tid >> 6, i = tid & 63;
            float u = s.Y[i * 3 + 0] * s.Si[0 + o]
                    + s.Y[i * 3 + 1] * s.Si[3 + o]
                    + s.Y[i * 3 + 2] * s.Si[6 + o];
            s.U[tid] = u;
            g_U[t * 192 + tid] = u;
            float dd = fabsf(u - s.Up[tid]);
            s.Up[tid] = u;
            atomicMax(&s.ctl[0], __float_as_int(dd));
            atomicMax(&s.ctl[1], __float_as_int(fabsf(u)));
        }
        __syncthreads();

        // ---- CP = C @ P (3x64), convergence decision ----
        if (tid < 192) {
            int o = tid >> 6, j = tid & 63;
            float acc = 0.f;
            for (int k = 0; k < 64; k++) acc += s.Cs[o * 64 + k] * s.P[k * PD + j];
            s.CP[tid] = acc;
        }
        if (tid == 0) {
            float md = __int_as_float(s.ctl[0]);
            float ma = __int_as_float(s.ctl[1]);
            if (md <= 1e-7f * ma) s.done = 1;
            s.ctl[0] = 0; s.ctl[1] = 0;
        }
        __syncthreads();

        // ---- cov = P - U^T (CP) ----
        for (int e = tid; e < 4096; e += 256) {
            int i = e >> 6, j = e & 63;
            s.cov[i * PD + j] = s.P[i * PD + j]
                - (s.U[i]       * s.CP[j]
                 + s.U[64 + i]  * s.CP[64 + j]
                 + s.U[128 + i] * s.CP[128 + j]);
        }
        __syncthreads();

        if (s.done) {   // stationary: fill remaining steps with fixed point
            for (int tt = t + 1; tt < TT; tt++)
                for (int idx = tid; idx < 192; idx += 256)
                    g_U[tt * 192 + idx] = s.U[idx];
            break;
        }
    }
}

// ======================================================================
// Consumer: 128 blocks x 4 rows; warp == batch row; no block barriers
// in the time loop. Thread (warp r, lane) owns h[j0], h[j0+1], j0=2*lane.
// ======================================================================
struct CSmem {
    float Wih[32 * 64];    // [k][j]  = W_ih[j][k]
    float Whh[64 * 64];    // [k][j]  = W_hh[j][k]
    float Wmlp[320 * 64];  // [m][j]  = W_mlp[j][m]
    float Cs[192];         // [o][j]
    float buf[NHIST][4][64];
    float hid[4][64];
    float xs[2][4][32];
};

__global__ void __launch_bounds__(128, 1)
seq_kernel(const float* __restrict__ x,
           const float* __restrict__ W_ih, const float* __restrict__ b_ih,
           const float* __restrict__ W_hh, const float* __restrict__ b_hh,
           const float* __restrict__ C,
           const float* __restrict__ W_mlp, const float* __restrict__ b_mlp,
           float* __restrict__ out, float* __restrict__ hlast) {
    extern __shared__ char craw[];
    CSmem& s = *reinterpret_cast<CSmem*>(craw);
    const int tid  = threadIdx.x;
    const int r    = tid >> 5;        // warp index == local row
    const int lane = tid & 31;
    const int j0   = lane * 2;
    const int row  = blockIdx.x * 4 + r;

    for (int idx = tid; idx < 2048; idx += 128) {
        int k = idx >> 6, j = idx & 63; s.Wih[idx] = W_ih[j * IDM + k];
    }
    for (int idx = tid; idx < 4096; idx += 128) {
        int k = idx >> 6, j = idx & 63; s.Whh[idx] = W_hh[j * HH + k];
    }
    for (int idx = tid; idx < 20480; idx += 128) {
        int m = idx >> 6, j = idx & 63; s.Wmlp[idx] = W_mlp[j * 320 + m];
    }
    for (int idx = tid; idx < 192; idx += 128) s.Cs[idx] = C[idx];
    for (int idx = tid; idx < NHIST * 4 * 64; idx += 128) (&s.buf[0][0][0])[idx] = 0.f;
    for (int idx = tid; idx < 256; idx += 128) (&s.hid[0][0])[idx] = 0.f;
    s.xs[0][r][lane] = x[(size_t)row * IDM + lane];   // x_0
    __syncthreads();

    const float ab0 = __ldg(&b_ih[j0])     + __ldg(&b_hh[j0]);
    const float ab1 = __ldg(&b_ih[j0 + 1]) + __ldg(&b_hh[j0 + 1]);
    const float mb0 = __ldg(&b_mlp[j0]),  mb1 = __ldg(&b_mlp[j0 + 1]);
    const float c0a = s.Cs[j0],       c0b = s.Cs[j0 + 1];
    const float c1a = s.Cs[64 + j0],  c1b = s.Cs[64 + j0 + 1];
    const float c2a = s.Cs[128 + j0], c2b = s.Cs[128 + j0 + 1];

    float h0 = 0.f, h1 = 0.f;
    int par = 0;

    for (int t = 0; t < TT; t++) {
        // prefetch x_{t+1}
        float xpf = 0.f;
        if (t + 1 < TT) xpf = x[((size_t)(t + 1) * BB + row) * IDM + lane];

        // ---- h = relu(x W_ih^T + hid W_hh^T + b), leaky blend ----
        float a0a = ab0, a1a = ab1, a0b = 0.f, a1b = 0.f;
        const float* xr = s.xs[par][r];
        #pragma unroll
        for (int k = 0; k < IDM; k += 2) {
            float va = xr[k], vb = xr[k + 1];
            float2 wa = *(const float2*)&s.Wih[k * HH + j0];
            float2 wb = *(const float2*)&s.Wih[(k + 1) * HH + j0];
            a0a += va * wa.x; a1a += va * wa.y;
            a0b += vb * wb.x; a1b += vb * wb.y;
        }
        const float* hr = s.hid[r];
        #pragma unroll 8
        for (int k = 0; k < HH; k += 2) {
            float va = hr[k], vb = hr[k + 1];
            float2 wa = *(const float2*)&s.Whh[k * HH + j0];
            float2 wb = *(const float2*)&s.Whh[(k + 1) * HH + j0];
            a0a += va * wa.x; a1a += va * wa.y;
            a0b += vb * wb.x; a1b += vb * wb.y;
        }
        float ho0 = h0 * 0.8f + fmaxf(a0a + a0b, 0.f) * 0.2f;
        float ho1 = h1 * 0.8f + fmaxf(a1a + a1b, 0.f) * 0.2f;

        if (t >= NHIST) {
            // ---- h_mlp over 5-slot circular history, oldest slot = t%5 ----
            float m0a = mb0, m1a = mb1, m0b = 0.f, m1b = 0.f;
            int base = t % NHIST;
            #pragma unroll
            for (int sdx = 0; sdx < NHIST; sdx++) {
                int slot = base + sdx; if (slot >= NHIST) slot -= NHIST;
                const float* bs = s.buf[slot][r];
                const float* wm = &s.Wmlp[sdx * HH * HH];
                #pragma unroll 8
                for (int k = 0; k < HH; k += 2) {
                    float va = bs[k], vb = bs[k + 1];
                    float2 wa = *(const float2*)&wm[k * HH + j0];
                    float2 wb = *(const float2*)&wm[(k + 1) * HH + j0];
                    m0a += va * wa.x; m1a += va * wa.y;
                    m0b += vb * wb.x; m1b += vb * wb.y;
                }
            }
            // ---- rank-3 correction: h += K (C (h_mlp - h_obs)) ----
            float d0 = (m0a + m0b) - ho0, d1 = (m1a + m1b) - ho1;
            float p0 = c0a * d0 + c0b * d1;
            float p1 = c1a * d0 + c1b * d1;
            float p2 = c2a * d0 + c2b * d1;
            #pragma unroll
            for (int off = 16; off; off >>= 1) {
                p0 += __shfl_xor_sync(0xffffffffu, p0, off);
                p1 += __shfl_xor_sync(0xffffffffu, p1, off);
                p2 += __shfl_xor_sync(0xffffffffu, p2, off);
            }
            const float* Ut = &g_U[t * 192];
            float2 k0 = *(const float2*)&Ut[j0];
            float2 k1 = *(const float2*)&Ut[64 + j0];
            float2 k2 = *(const float2*)&Ut[128 + j0];
            ho0 += k0.x * p0 + k1.x * p1 + k2.x * p2;
            ho1 += k0.y * p0 + k1.y * p1 + k2.y * p2;
        }

        __syncwarp();   // all history/hid reads done before overwrite
        int ws = t % NHIST;
        *(float2*)&s.buf[ws][r][j0] = make_float2(ho0, ho1);
        *(float2*)&s.hid[r][j0]     = make_float2(ho0, ho1);
        s.xs[par ^ 1][r][lane] = xpf;
        *(float2*)&out[((size_t)t * BB + row) * HH + j0] = make_float2(ho0, ho1);
        h0 = ho0; h1 = ho1; par ^= 1;
        __syncwarp();   // writes visible before next step's reads
    }

    if (hlast) *(float2*)&hlast[(size_t)row * HH + j0] = make_float2(h0, h1);
}

// ======================================================================
extern "C" void kernel_launch(void* const* d_in, const int* in_sizes, int n_in,
                              void* d_out, int out_size) {
    const float* x     = (const float*)d_in[0];
    const float* W_ih  = (const float*)d_in[1];
    const float* b_ih  = (const float*)d_in[2];
    const float* W_hh  = (const float*)d_in[3];
    const float* b_hh  = (const float*)d_in[4];
    const float* C     = (const float*)d_in[5];
    const float* W_mlp = (const float*)d_in[6];
    const float* b_mlp = (const float*)d_in[7];
    float* out = (float*)d_out;

    const long long main_elems = (long long)TT * BB * HH;
    float* hlast = ((long long)out_size >= main_elems + (long long)BB * HH)
                       ? out + main_elems : nullptr;

    cudaFuncSetAttribute(cov_kernel, cudaFuncAttributeMaxDynamicSharedMemorySize,
                         (int)sizeof(PSmem));
    cudaFuncSetAttribute(seq_kernel, cudaFuncAttributeMaxDynamicSharedMemorySize,
                         (int)sizeof(CSmem));

    cov_kernel<<<1, 256, sizeof(PSmem)>>>(W_hh, C);
    seq_kernel<<<BB / 4, 128, sizeof(CSmem)>>>(x, W_ih, b_ih, W_hh, b_hh, C,
                                               W_mlp, b_mlp, out, hlast);
}